// round 15
// baseline (speedup 1.0000x reference)
#include <cuda_runtime.h>
#include <cstdint>

#define FULL_MASK 0xFFFFFFFFu

constexpr int B_ = 2048;
constexpr int L_ = 2048;
constexpr float LOG2E_F = 1.4426950408889634f;
constexpr float LN2_F   = 0.6931471805599453f;

// device scratch (no allocation allowed)
__device__ int g_len[B_], g_order[B_];
__device__ __align__(16) float g_alpha[B_ * 8];
__device__ __align__(16) float g_beta [B_ * 8];
__device__ float g_cf[B_], g_cb[B_], g_numf[B_], g_numb[B_];

__device__ __forceinline__ float fx2(float x)
{ float r; asm("ex2.approx.ftz.f32 %0, %1;" : "=f"(r) : "f"(x)); return r; }
__device__ __forceinline__ float fexp(float x) { return fx2(x * LOG2E_F); }
__device__ __forceinline__ void l2pf(const void* p)
{ asm volatile("prefetch.global.L2 [%0];" :: "l"(p)); }

// select component s (0..3) of a float4 (pure SEL tree, no local mem)
__device__ __forceinline__ float sel4(float4 v, int s)
{
    float ab = (s & 1) ? v.y : v.x;
    float cd = (s & 1) ? v.w : v.z;
    return (s & 2) ? cd : ab;
}

// ---------------- kernel 1: sequence lengths ----------------
__global__ void scan_len(const int* __restrict__ tags)
{
    int w    = blockIdx.x * 8 + (threadIdx.x >> 5);
    int lane = threadIdx.x & 31;
    const int4* p = (const int4*)(tags + (size_t)w * L_ + 1024);
    int firstz = 1024;
    #pragma unroll
    for (int k = 0; k < 8; k++) {
        int4 v = p[k * 32 + lane];
        int base = (k * 32 + lane) * 4;
        if (v.w == 0) firstz = min(firstz, base + 3);
        if (v.z == 0) firstz = min(firstz, base + 2);
        if (v.y == 0) firstz = min(firstz, base + 1);
        if (v.x == 0) firstz = min(firstz, base + 0);
    }
    firstz = __reduce_min_sync(FULL_MASK, firstz);
    if (lane == 0) g_len[w] = 1024 + firstz;
}

// ---------------- kernel 2: length-sorted order (all-pairs rank, deterministic) ----
__global__ void rank_order()
{
    __shared__ int s_len[B_];
    for (int i = threadIdx.x; i < B_; i += blockDim.x) s_len[i] = g_len[i];
    __syncthreads();
    int b   = blockIdx.x * blockDim.x + threadIdx.x;   // 16x128 -> 2048 threads
    int myl = s_len[b];
    int r = 0;
    #pragma unroll 8
    for (int i = 0; i < B_; i++) {
        int li = s_len[i];
        r += (li < myl) || (li == myl && i < b);
    }
    g_order[r] = b;
}

// ---------------- kernel 3: 2 lanes/chain, 16 chains/warp, branchless ----------------
__global__ __launch_bounds__(128, 1)
void crf_chains(const float* __restrict__ em, const float* __restrict__ trans,
                const float* __restrict__ startT, const float* __restrict__ endT,
                const int* __restrict__ tags)
{
    __shared__ float s_tr[64];
    int tid = threadIdx.x;
    if (tid < 64) s_tr[tid] = trans[tid];
    __syncthreads();

    int lane = tid & 31;
    int h    = lane & 1;                               // half owner (0: states 0-3, 1: 4-7)
    int gw   = blockIdx.x * 4 + (tid >> 5);            // 0..255
    bool is_bwd = (gw >= 128);
    int b   = g_order[(gw & 127) * 16 + (lane >> 1)];
    int len = g_len[b];
    int mid = len >> 1;                                // fwd: t=0..mid, bwd: (mid, len-1]
    int o0  = h * 4, p0 = 4 - o0;

    const float* emB = em   + (size_t)b * (L_ * 8) + o0;   // own-half base
    const int*   tgB = tags + (size_t)b * L_;

    float W[4][4], V[4][4];
    float a0, a1, a2, a3, c = 0.0f, num = 0.0f;
    float4 eA[4], eB[4];
    int    tA[4], tB[4];

    if (!is_bwd) {
        // ==== FORWARD: a_new[o] = (sum_k a_k E[k][o]) * exp(em_t[o]) ====
        #pragma unroll
        for (int k = 0; k < 4; k++)
            #pragma unroll
            for (int o = 0; o < 4; o++) {
                W[k][o] = fexp(s_tr[(o0 + k) * 8 + o0 + o]);
                V[k][o] = fexp(s_tr[(p0 + k) * 8 + o0 + o]);
            }
        float4 em0 = __ldg((const float4*)emB);
        a0 = fexp(__ldg(&startT[o0 + 0]) + em0.x);
        a1 = fexp(__ldg(&startT[o0 + 1]) + em0.y);
        a2 = fexp(__ldg(&startT[o0 + 2]) + em0.z);
        a3 = fexp(__ldg(&startT[o0 + 3]) + em0.w);
        int s_prev = __ldg(&tgB[0]) - 1;               // len>=1024 => tag0 != 0
        num = ((s_prev >> 2) == h) ? (__ldg(&startT[s_prev]) + sel4(em0, s_prev & 3)) : 0.0f;

        int m_hi = __reduce_max_sync(FULL_MASK, mid);

        #pragma unroll
        for (int u = 0; u < 4; u++) { eA[u] = __ldg((const float4*)(emB + (size_t)(1 + u) * 8)); tA[u] = __ldg(&tgB[1 + u]); }
        #pragma unroll
        for (int u = 0; u < 4; u++) { eB[u] = __ldg((const float4*)(emB + (size_t)(5 + u) * 8)); tB[u] = __ldg(&tgB[5 + u]); }

        for (int t = 1; t <= m_hi; t += 8) {
            l2pf(emB + (size_t)(t + 24) * 8);
            if (h == 0) l2pf(&tgB[t + 24]);
            #pragma unroll
            for (int half = 0; half < 2; half++) {
                #pragma unroll
                for (int u = 0; u < 4; u++) {
                    float4 e = half ? eB[u] : eA[u];
                    int tg   = half ? tB[u] : tA[u];
                    int tt   = t + half * 4 + u;
                    float ex0 = fexp(e.x), ex1 = fexp(e.y), ex2 = fexp(e.z), ex3 = fexp(e.w);
                    float xs0 = __shfl_xor_sync(FULL_MASK, a0, 1);
                    float xs1 = __shfl_xor_sync(FULL_MASK, a1, 1);
                    float xs2 = __shfl_xor_sync(FULL_MASK, a2, 1);
                    float xs3 = __shfl_xor_sync(FULL_MASK, a3, 1);
                    float cd[4];
                    #pragma unroll
                    for (int o = 0; o < 4; o++) {
                        float s = a0 * W[0][o];
                        s = fmaf(a1, W[1][o], s);
                        s = fmaf(a2, W[2][o], s);
                        s = fmaf(a3, W[3][o], s);
                        s = fmaf(xs0, V[0][o], s);
                        s = fmaf(xs1, V[1][o], s);
                        s = fmaf(xs2, V[2][o], s);
                        s = fmaf(xs3, V[3][o], s);
                        cd[o] = s;
                    }
                    bool act = (tt <= mid);
                    a0 = act ? cd[0] * ex0 : a0;
                    a1 = act ? cd[1] * ex1 : a1;
                    a2 = act ? cd[2] * ex2 : a2;
                    a3 = act ? cd[3] * ex3 : a3;
                    int st = tg - 1;
                    float addv = s_tr[(s_prev << 3) | st] + sel4(e, st & 3);
                    num += (act && ((st >> 2) == h)) ? addv : 0.0f;
                    s_prev = act ? st : s_prev;
                }
                // reload the just-consumed half: A <- t+8..t+11, B <- t+12..t+15 (max 1039 < 2048)
                #pragma unroll
                for (int u = 0; u < 4; u++) {
                    int q = t + 8 + half * 4 + u;
                    if (half) { eB[u] = __ldg((const float4*)(emB + (size_t)q * 8)); tB[u] = __ldg(&tgB[q]); }
                    else      { eA[u] = __ldg((const float4*)(emB + (size_t)q * 8)); tA[u] = __ldg(&tgB[q]); }
                }
            }
            float ae = __shfl_sync(FULL_MASK, a0, 0, 2);
            int ebx = __float_as_int(ae) & 0x7f800000;
            c += (float)((ebx >> 23) - 127);
            float sc = __int_as_float(0x7f000000 - ebx);   // exact 2^{-e}
            a0 *= sc; a1 *= sc; a2 *= sc; a3 *= sc;
        }
        g_alpha[b * 8 + o0 + 0] = a0; g_alpha[b * 8 + o0 + 1] = a1;
        g_alpha[b * 8 + o0 + 2] = a2; g_alpha[b * 8 + o0 + 3] = a3;
        num += __shfl_xor_sync(FULL_MASK, num, 1);
        if (h == 0) { g_cf[b] = c; g_numf[b] = num; }
    } else {
        // ==== BACKWARD: b_new[o] = sum_k E[o0+o][k] * exp(em_t[k]) * b[k] ====
        #pragma unroll
        for (int k = 0; k < 4; k++)
            #pragma unroll
            for (int o = 0; o < 4; o++) {
                W[k][o] = fexp(s_tr[(o0 + o) * 8 + o0 + k]);
                V[k][o] = fexp(s_tr[(o0 + o) * 8 + p0 + k]);
            }
        float en0 = __ldg(&endT[o0 + 0]), en1 = __ldg(&endT[o0 + 1]);
        float en2 = __ldg(&endT[o0 + 2]), en3 = __ldg(&endT[o0 + 3]);
        float4 enr = make_float4(en0, en1, en2, en3);
        a0 = fexp(en0); a1 = fexp(en1); a2 = fexp(en2); a3 = fexp(en3);
        int s_succ = 0;

        int t0   = __reduce_max_sync(FULL_MASK, len) - 1;
        int tmin = __reduce_min_sync(FULL_MASK, mid) + 1;

        #pragma unroll
        for (int u = 0; u < 4; u++) { int q = t0 - u;     eA[u] = __ldg((const float4*)(emB + (size_t)q * 8)); tA[u] = __ldg(&tgB[q]); }
        #pragma unroll
        for (int u = 0; u < 4; u++) { int q = t0 - 4 - u; eB[u] = __ldg((const float4*)(emB + (size_t)q * 8)); tB[u] = __ldg(&tgB[q]); }

        for (int t = t0; t >= tmin; t -= 8) {
            l2pf(emB + (size_t)(t - 24) * 8);          // min (tmin-24)*8 >= (513-24)*8 > 0
            if (h == 0) l2pf(&tgB[t - 24]);
            #pragma unroll
            for (int half = 0; half < 2; half++) {
                #pragma unroll
                for (int u = 0; u < 4; u++) {
                    float4 e = half ? eB[u] : eA[u];
                    int tg   = half ? tB[u] : tA[u];
                    int tt   = t - half * 4 - u;
                    float q0 = a0 * fexp(e.x), q1 = a1 * fexp(e.y);
                    float q2 = a2 * fexp(e.z), q3 = a3 * fexp(e.w);
                    float xs0 = __shfl_xor_sync(FULL_MASK, q0, 1);
                    float xs1 = __shfl_xor_sync(FULL_MASK, q1, 1);
                    float xs2 = __shfl_xor_sync(FULL_MASK, q2, 1);
                    float xs3 = __shfl_xor_sync(FULL_MASK, q3, 1);
                    float cd[4];
                    #pragma unroll
                    for (int o = 0; o < 4; o++) {
                        float s = q0 * W[0][o];
                        s = fmaf(q1, W[1][o], s);
                        s = fmaf(q2, W[2][o], s);
                        s = fmaf(q3, W[3][o], s);
                        s = fmaf(xs0, V[0][o], s);
                        s = fmaf(xs1, V[1][o], s);
                        s = fmaf(xs2, V[2][o], s);
                        s = fmaf(xs3, V[3][o], s);
                        cd[o] = s;
                    }
                    bool act = (tt > mid) && (tt < len);
                    a0 = act ? cd[0] : a0; a1 = act ? cd[1] : a1;
                    a2 = act ? cd[2] : a2; a3 = act ? cd[3] : a3;
                    int st = tg - 1;
                    float tr = s_tr[(st << 3) | s_succ];
                    float ev = sel4(enr, st & 3);
                    float addv = sel4(e, st & 3) + ((tt == len - 1) ? ev : tr);
                    num += (act && ((st >> 2) == h)) ? addv : 0.0f;
                    s_succ = act ? st : s_succ;
                }
                // reload consumed half: A <- t-8.., B <- t-12.. (min tmin-15 >= 498 > 0)
                #pragma unroll
                for (int u = 0; u < 4; u++) {
                    int q = t - 8 - half * 4 - u;
                    if (half) { eB[u] = __ldg((const float4*)(emB + (size_t)q * 8)); tB[u] = __ldg(&tgB[q]); }
                    else      { eA[u] = __ldg((const float4*)(emB + (size_t)q * 8)); tA[u] = __ldg(&tgB[q]); }
                }
            }
            float ae = __shfl_sync(FULL_MASK, a0, 0, 2);
            int ebx = __float_as_int(ae) & 0x7f800000;
            c += (float)((ebx >> 23) - 127);
            float sc = __int_as_float(0x7f000000 - ebx);
            a0 *= sc; a1 *= sc; a2 *= sc; a3 *= sc;
        }
        // missing transition (s_mid -> s_{mid+1}); s_succ == s_{mid+1}
        int s_m = __ldg(&tgB[mid]) - 1;
        num += (h == 0) ? s_tr[(s_m << 3) | s_succ] : 0.0f;

        g_beta[b * 8 + o0 + 0] = a0; g_beta[b * 8 + o0 + 1] = a1;
        g_beta[b * 8 + o0 + 2] = a2; g_beta[b * 8 + o0 + 3] = a3;
        num += __shfl_xor_sync(FULL_MASK, num, 1);
        if (h == 0) { g_cb[b] = c; g_numb[b] = num; }
    }
}

// ---------------- kernel 4: combine halves + deterministic mean ----------------
__global__ void crf_combine(float* __restrict__ out)
{
    __shared__ float sb[1024];
    int tid = threadIdx.x;
    float acc = 0.0f;
    #pragma unroll
    for (int it = 0; it < 2; it++) {
        int b = tid + it * 1024;                       // fixed per-thread order
        const float4* pa = (const float4*)&g_alpha[b * 8];
        const float4* pw = (const float4*)&g_beta[b * 8];
        float4 x0 = pa[0], x1 = pa[1], w0 = pw[0], w1 = pw[1];
        float Z = x0.x * w0.x + x0.y * w0.y + x0.z * w0.z + x0.w * w0.w
                + x1.x * w1.x + x1.y * w1.y + x1.z * w1.z + x1.w * w1.w;
        acc += g_numf[b] + g_numb[b] - LN2_F * (g_cf[b] + g_cb[b] + __log2f(Z));
    }
    sb[tid] = acc;
    __syncthreads();
    for (int k = 512; k > 0; k >>= 1) {
        if (tid < k) sb[tid] += sb[tid + k];
        __syncthreads();
    }
    if (tid == 0) out[0] = -sb[0] * (1.0f / (float)B_);
}

extern "C" void kernel_launch(void* const* d_in, const int* in_sizes, int n_in,
                              void* d_out, int out_size)
{
    const float* em    = (const float*)d_in[0];   // (B, L, T) f32
    const float* trans = (const float*)d_in[1];   // (T, T)    f32
    const float* st    = (const float*)d_in[2];   // (T,)      f32
    const float* en    = (const float*)d_in[3];   // (T,)      f32
    const int*   tags  = (const int*)  d_in[4];   // (B, L)    int32

    scan_len   <<<256, 256>>>(tags);
    rank_order <<<16, 128>>>();
    crf_chains <<<64, 128>>>(em, trans, st, en, tags);
    crf_combine<<<1, 1024>>>((float*)d_out);
}